// round 12
// baseline (speedup 1.0000x reference)
#include <cuda_runtime.h>
#include <cuda_bf16.h>
#include <cstdint>

#define NN 50000
#define NE 800000
#define NG 500
#define NBLK_SCAN 196   // ceil(NN/256)

// ==================== device scratch ====================
__device__ float g_ab[NN * 128];
__device__ float g_amp[NN];
__device__ int   g_hist[NN];
__device__ int   g_rowptr[NN + 1];
__device__ int   g_woff[NN];
__device__ int   g_bsum[256];
__device__ int   g_srcs[NE];
__device__ float g_W13[3 * 833 * 64];              // [layer][k<=832][j]; k=832 -> b13
__device__ __nv_bfloat16 g_A[(size_t)NN * 320];    // [node][5*64] hi: h|mean|mx|mn|std
__device__ __nv_bfloat16 g_Al[(size_t)NN * 320];   // lo
__device__ __nv_bfloat16 g_B[3 * 2 * 13 * 4096];   // [layer][part][tile][j][k]
__device__ __nv_bfloat16 g_Bp[3 * 2 * 2 * 4096];   // [layer][part][tile][j][k]
__device__ float g_pool[NG * 64];
__device__ float g_gcnt[NG];

__device__ __forceinline__ void bsplit(float v, __nv_bfloat16& h, __nv_bfloat16& l) {
    h = __float2bfloat16(v);
    l = __float2bfloat16(v - __bfloat162float(h));
}
__device__ __forceinline__ uint16_t bbits(__nv_bfloat16 h) {
    return *reinterpret_cast<uint16_t*>(&h);
}

// ==================== setup ====================
__global__ void zero_front_kernel() {
    int i = blockIdx.x * blockDim.x + threadIdx.x;
    if (i < NN) g_hist[i] = 0;
    if (i < NG * 64) g_pool[i] = 0.f;
    if (i < NG) g_gcnt[i] = 0.f;
}
__global__ void split_x_kernel(const float* __restrict__ x) {
    int i = blockIdx.x * blockDim.x + threadIdx.x;
    if (i < NN * 64) {
        int n = i >> 6, c = i & 63;
        __nv_bfloat16 h, l;
        bsplit(x[i], h, l);
        g_A[(size_t)n * 320 + c] = h;
        g_Al[(size_t)n * 320 + c] = l;
    }
}

// ==================== weight prep (all 3 layers up front) ====================
__global__ void fold_all_kernel(const float* __restrict__ post_w, const float* __restrict__ post_b,
                                const float* __restrict__ lin_w, const float* __restrict__ lin_b) {
    int idx = blockIdx.x * blockDim.x + threadIdx.x;
    if (idx >= 3 * 833 * 64) return;
    int layer = idx / (833 * 64);
    int r = idx % (833 * 64);
    int k = r >> 6, j = r & 63;
    const float* ow = post_w + layer * 832 * 64;
    const float* lw = lin_w + layer * 64 * 64;
    if (k < 832) {
        float s = 0.f;
        for (int c = 0; c < 64; c++) s = fmaf(ow[k * 64 + c], lw[c * 64 + j], s);
        g_W13[idx] = s;
    } else {
        float s = lin_b[layer * 64 + j];
        for (int c = 0; c < 64; c++) s = fmaf(post_b[layer * 64 + c], lw[c * 64 + j], s);
        g_W13[idx] = s;
    }
}
__global__ void pack_all_kernel(const float* __restrict__ pre_w) {
    int idx = blockIdx.x * blockDim.x + threadIdx.x;
    if (idx < 3 * 13 * 4096) {
        int layer = idx / (13 * 4096);
        int r = idx % (13 * 4096);
        int tile = r >> 12, q = r & 4095;
        int j = q >> 6, k = q & 63;
        float w = g_W13[layer * 833 * 64 + (tile * 64 + k) * 64 + j];
        __nv_bfloat16 h, l;
        bsplit(w, h, l);
        g_B[((size_t)(layer * 2 + 0) * 13 + tile) * 4096 + q] = h;
        g_B[((size_t)(layer * 2 + 1) * 13 + tile) * 4096 + q] = l;
    } else if (idx < 3 * 13 * 4096 + 3 * 2 * 4096) {
        int i2 = idx - 3 * 13 * 4096;
        int layer = i2 / (2 * 4096);
        int r = i2 % (2 * 4096);
        int tile = r >> 12, q = r & 4095;
        int j = q >> 6, k = q & 63;
        float w = pre_w[layer * 128 * 64 + (tile * 64 + k) * 64 + j];
        __nv_bfloat16 h, l;
        bsplit(w, h, l);
        g_Bp[((size_t)(layer * 2 + 0) * 2 + tile) * 4096 + q] = h;
        g_Bp[((size_t)(layer * 2 + 1) * 2 + tile) * 4096 + q] = l;
    }
}

// ==================== CSR build ====================
__global__ void hist_kernel(const int* __restrict__ dst) {
    int e = blockIdx.x * blockDim.x + threadIdx.x;
    if (e < NE) atomicAdd(&g_hist[dst[e]], 1);
}
__global__ void scan1_kernel() {
    int b = blockIdx.x, t = threadIdx.x, i = b * 256 + t;
    int v = (i < NN) ? g_hist[i] : 0;
    int s = v;
#pragma unroll
    for (int o = 1; o < 32; o <<= 1) {
        int u = __shfl_up_sync(0xffffffffu, s, o);
        if ((t & 31) >= o) s += u;
    }
    __shared__ int wsum[8];
    if ((t & 31) == 31) wsum[t >> 5] = s;
    __syncthreads();
    if (t < 32) {
        int ws_ = (t < 8) ? wsum[t] : 0;
#pragma unroll
        for (int o = 1; o < 8; o <<= 1) {
            int u = __shfl_up_sync(0xffffffffu, ws_, o);
            if (t >= o) ws_ += u;
        }
        if (t < 8) wsum[t] = ws_;
    }
    __syncthreads();
    int incl = s + ((t >= 32) ? wsum[(t >> 5) - 1] : 0);
    if (i < NN) g_rowptr[i] = incl - v;
    if (t == 255) g_bsum[b] = incl;
}
__global__ void scan2_kernel() {
    int t = threadIdx.x;
    int v = (t < NBLK_SCAN) ? g_bsum[t] : 0;
    int s = v;
#pragma unroll
    for (int o = 1; o < 32; o <<= 1) {
        int u = __shfl_up_sync(0xffffffffu, s, o);
        if ((t & 31) >= o) s += u;
    }
    __shared__ int wsum[8];
    if ((t & 31) == 31) wsum[t >> 5] = s;
    __syncthreads();
    if (t < 32) {
        int ws_ = (t < 8) ? wsum[t] : 0;
#pragma unroll
        for (int o = 1; o < 8; o <<= 1) {
            int u = __shfl_up_sync(0xffffffffu, ws_, o);
            if (t >= o) ws_ += u;
        }
        if (t < 8) wsum[t] = ws_;
    }
    __syncthreads();
    int incl = s + ((t >= 32) ? wsum[(t >> 5) - 1] : 0);
    if (t < NBLK_SCAN) g_bsum[t] = incl - v;
    if (t == 0) g_rowptr[NN] = NE;
}
__global__ void scan3_kernel() {
    int i = blockIdx.x * 256 + threadIdx.x;
    if (i < NN) {
        int r = g_rowptr[i] + g_bsum[blockIdx.x];
        g_rowptr[i] = r;
        g_woff[i] = r;
        float degc = fmaxf((float)g_hist[i], 1.f);
        g_amp[i] = logf(degc + 1.f) * 0.35295612f;
    }
}
__global__ void scatter_kernel(const int* __restrict__ dst, const int* __restrict__ src) {
    int e = blockIdx.x * blockDim.x + threadIdx.x;
    if (e < NE) {
        int d = dst[e];
        int pos = atomicAdd(&g_woff[d], 1);
        g_srcs[pos] = src[e];
    }
}

// ==================== mma helpers ====================
__device__ __forceinline__ void mma16816(float* d, uint32_t a0, uint32_t a1, uint32_t a2,
                                         uint32_t a3, uint32_t b0, uint32_t b1) {
    asm("mma.sync.aligned.m16n8k16.row.col.f32.bf16.bf16.f32 "
        "{%0,%1,%2,%3}, {%4,%5,%6,%7}, {%8,%9}, {%0,%1,%2,%3};"
        : "+f"(d[0]), "+f"(d[1]), "+f"(d[2]), "+f"(d[3])
        : "r"(a0), "r"(a1), "r"(a2), "r"(a3), "r"(b0), "r"(b1));
}
__device__ __forceinline__ void ldsm4(uint32_t& r0, uint32_t& r1, uint32_t& r2, uint32_t& r3,
                                      uint32_t saddr) {
    asm volatile("ldmatrix.sync.aligned.m8n8.x4.shared.b16 {%0,%1,%2,%3}, [%4];"
                 : "=r"(r0), "=r"(r1), "=r"(r2), "=r"(r3) : "r"(saddr));
}

// ==================== pre-GEMM (layer 0 only, proven LDS path) ====================
#define PRE_SMEM_B (2304 * 6 * 4)
__global__ void __launch_bounds__(256)
pre_mma_kernel(int layer, const float* __restrict__ pb) {
    extern __shared__ uint32_t smw[];
    uint32_t* Ah = smw;
    uint32_t* Alo = smw + 2304;
    int t = threadIdx.x, lane = t & 31, w = t >> 5;
    int ws = w >> 1, wc = w & 1;
    int node0 = blockIdx.x * 64;
    const uint4* GA4 = (const uint4*)g_A;
    const uint4* GAl4 = (const uint4*)g_Al;
    const uint4* GBp4 = (const uint4*)g_Bp;

    for (int i = t; i < 512; i += 256) {
        int row = i >> 3, seg = i & 7;
        int n = node0 + row;
        if (n > NN - 1) n = NN - 1;
        uint4 va = GA4[(size_t)n * 40 + seg];
        uint4 vl = GAl4[(size_t)n * 40 + seg];
        *(uint4*)(Ah + row * 36 + seg * 4) = va;
        *(uint4*)(Alo + row * 36 + seg * 4) = vl;
    }
    for (int i = t; i < 2048; i += 256) {
        int tidx = i >> 9, r = i & 511;
        int row = r >> 3, seg = r & 7;
        uint4 v = GBp4[((size_t)(layer * 2 + (tidx >> 1)) * 2 + (tidx & 1)) * 512 + r];
        *(uint4*)(smw + 4608 + tidx * 2304 + row * 36 + seg * 4) = v;
    }
    __syncthreads();

    float d[2][4][4];
#pragma unroll
    for (int s = 0; s < 2; s++)
#pragma unroll
        for (int nt = 0; nt < 4; nt++)
#pragma unroll
            for (int q = 0; q < 4; q++) d[s][nt][q] = 0.f;

    int ra = ws * 16 + (lane >> 2);
#pragma unroll 1
    for (int ks = 0; ks < 4; ks++) {
        int kw = ks * 8 + (lane & 3);
        uint32_t ah0 = Ah[ra * 36 + kw],      ah1 = Ah[(ra + 8) * 36 + kw];
        uint32_t ah2 = Ah[ra * 36 + kw + 4],  ah3 = Ah[(ra + 8) * 36 + kw + 4];
        uint32_t al0 = Alo[ra * 36 + kw],     al1 = Alo[(ra + 8) * 36 + kw];
        uint32_t al2 = Alo[ra * 36 + kw + 4], al3 = Alo[(ra + 8) * 36 + kw + 4];
#pragma unroll
        for (int s = 0; s < 2; s++) {
            const uint32_t* Bh = smw + 4608 + s * 2304;
            const uint32_t* Bl = smw + 4608 + (2 + s) * 2304;
#pragma unroll
            for (int nt = 0; nt < 4; nt++) {
                int bi = (wc * 32 + nt * 8 + (lane >> 2)) * 36 + kw;
                uint32_t bh0 = Bh[bi], bh1 = Bh[bi + 4];
                uint32_t bl0 = Bl[bi], bl1 = Bl[bi + 4];
                mma16816(d[s][nt], ah0, ah1, ah2, ah3, bh0, bh1);
                mma16816(d[s][nt], al0, al1, al2, al3, bh0, bh1);
                mma16816(d[s][nt], ah0, ah1, ah2, ah3, bl0, bl1);
            }
        }
    }
#pragma unroll
    for (int half = 0; half < 2; half++) {
        int node = node0 + ra + half * 8;
        if (node >= NN) continue;
#pragma unroll
        for (int s = 0; s < 2; s++)
#pragma unroll
            for (int nt = 0; nt < 4; nt++) {
                int col = wc * 32 + nt * 8 + (lane & 3) * 2;
                float y0 = d[s][nt][2 * half], y1 = d[s][nt][2 * half + 1];
                if (s == 0) { y0 += pb[col]; y1 += pb[col + 1]; }
                *(float2*)(g_ab + (size_t)node * 128 + s * 64 + col) = make_float2(y0, y1);
            }
    }
}

// ==================== aggregation: 2 edges/iter via LDG.128 ====================
__global__ void agg_kernel() {
    int n = (blockIdx.x * blockDim.x + threadIdx.x) >> 5;
    if (n >= NN) return;
    int lane = threadIdx.x & 31;
    int half = lane >> 4, hl = lane & 15;
    int s0 = g_rowptr[n], s1 = g_rowptr[n + 1];
    int deg = s1 - s0;
    float S1[4] = {0.f, 0.f, 0.f, 0.f}, S2[4] = {0.f, 0.f, 0.f, 0.f};
    float MX[4] = {-3.4e38f, -3.4e38f, -3.4e38f, -3.4e38f};
    float MN[4] = {3.4e38f, 3.4e38f, 3.4e38f, 3.4e38f};
    for (int e = s0 + half; e < s1; e += 2) {
        int src = g_srcs[e];
        float4 v = *(const float4*)(g_ab + (size_t)src * 128 + 64 + hl * 4);
        S1[0] += v.x; S2[0] = fmaf(v.x, v.x, S2[0]); MX[0] = fmaxf(MX[0], v.x); MN[0] = fminf(MN[0], v.x);
        S1[1] += v.y; S2[1] = fmaf(v.y, v.y, S2[1]); MX[1] = fmaxf(MX[1], v.y); MN[1] = fminf(MN[1], v.y);
        S1[2] += v.z; S2[2] = fmaf(v.z, v.z, S2[2]); MX[2] = fmaxf(MX[2], v.z); MN[2] = fminf(MN[2], v.z);
        S1[3] += v.w; S2[3] = fmaf(v.w, v.w, S2[3]); MX[3] = fmaxf(MX[3], v.w); MN[3] = fminf(MN[3], v.w);
    }
#pragma unroll
    for (int q = 0; q < 4; q++) {
        S1[q] += __shfl_xor_sync(0xffffffffu, S1[q], 16);
        S2[q] += __shfl_xor_sync(0xffffffffu, S2[q], 16);
        MX[q] = fmaxf(MX[q], __shfl_xor_sync(0xffffffffu, MX[q], 16));
        MN[q] = fminf(MN[q], __shfl_xor_sync(0xffffffffu, MN[q], 16));
    }
    float4 av = *(const float4*)(g_ab + (size_t)n * 128 + hl * 4);
    float a[4] = {av.x, av.y, av.z, av.w};
    float degf = (float)deg, degc = fmaxf(degf, 1.f), rdeg = 1.f / degc;
    size_t base = (size_t)n * 320;
#pragma unroll
    for (int which = 0; which < 2; which++) {
        float v[4];
        int s;
        if (half == 0) {
            if (which == 0) {
                s = 0;
#pragma unroll
                for (int q = 0; q < 4; q++) v[q] = (degf * a[q] + S1[q]) * rdeg;
            } else {
                s = 1;
#pragma unroll
                for (int q = 0; q < 4; q++) v[q] = (deg > 0) ? a[q] + MX[q] : 0.f;
            }
        } else {
            if (which == 0) {
                s = 2;
#pragma unroll
                for (int q = 0; q < 4; q++) v[q] = (deg > 0) ? a[q] + MN[q] : 0.f;
            } else {
                s = 3;
#pragma unroll
                for (int q = 0; q < 4; q++) {
                    float mean = (degf * a[q] + S1[q]) * rdeg;
                    float msq = (degf * a[q] * a[q] + 2.f * a[q] * S1[q] + S2[q]) * rdeg;
                    v[q] = sqrtf(fmaxf(msq - mean * mean, 0.f) + 1e-5f);
                }
            }
        }
        uint32_t hu0, hu1, lu0, lu1;
        __nv_bfloat16 hh, ll;
        bsplit(v[0], hh, ll); hu0 = bbits(hh); lu0 = bbits(ll);
        bsplit(v[1], hh, ll); hu0 |= (uint32_t)bbits(hh) << 16; lu0 |= (uint32_t)bbits(ll) << 16;
        bsplit(v[2], hh, ll); hu1 = bbits(hh); lu1 = bbits(ll);
        bsplit(v[3], hh, ll); hu1 |= (uint32_t)bbits(hh) << 16; lu1 |= (uint32_t)bbits(ll) << 16;
        size_t o = base + (size_t)(1 + s) * 64 + hl * 4;
        *(uint2*)(g_A + o) = make_uint2(hu0, hu1);
        *(uint2*)(g_Al + o) = make_uint2(lu0, lu1);
    }
}

// ==================== node GEMM M=128 + fused LN/pool + fused next-layer pre ====
// smem words: main Ah@0 (4608), Alo@4608, B 6x2304 @9216..23039
// epilogue: F floats @0 (8704 w), preAh@9216, preAl@13824, preB 4x2304 @18432..27647
#define NODE_SMEM_W 27648
#define NODE_SMEM_B (NODE_SMEM_W * 4)

__global__ void __launch_bounds__(256)
node_mma_kernel(int layer, int do_ln, const float* __restrict__ lnw,
                const float* __restrict__ lnb, const int* __restrict__ batch,
                const float* __restrict__ pbn) {
    extern __shared__ uint32_t smw[];
    uint32_t* Ah = smw;
    uint32_t* Alo = smw + 4608;
    int t = threadIdx.x, lane = t & 31, w = t >> 5;
    int node0 = blockIdx.x * 128;

    float d[3][8][4];
#pragma unroll
    for (int s = 0; s < 3; s++)
#pragma unroll
        for (int nt = 0; nt < 8; nt++)
#pragma unroll
            for (int q = 0; q < 4; q++) d[s][nt][q] = 0.f;

    const uint4* GA4 = (const uint4*)g_A;
    const uint4* GAl4 = (const uint4*)g_Al;
    const uint4* GB4 = (const uint4*)g_B;

    uint32_t sAh = (uint32_t)__cvta_generic_to_shared(Ah);
    uint32_t sAl = (uint32_t)__cvta_generic_to_shared(Alo);
    uint32_t sB0 = (uint32_t)__cvta_generic_to_shared(smw + 9216);

    int m = lane >> 3, rr = lane & 7;

    for (int c = 0; c < 5; c++) {
        __syncthreads();
        for (int i = t; i < 1024; i += 256) {
            int row = i >> 3, seg = i & 7;
            int n = node0 + row;
            if (n > NN - 1) n = NN - 1;
            uint4 va = GA4[(size_t)n * 40 + c * 8 + seg];
            uint4 vl = GAl4[(size_t)n * 40 + c * 8 + seg];
            *(uint4*)(Ah + row * 36 + seg * 4) = va;
            *(uint4*)(Alo + row * 36 + seg * 4) = vl;
        }
        int nsets = (c == 0) ? 1 : 3;
        for (int s = 0; s < nsets; s++) {
            int tile = (s == 0) ? c : (s == 1) ? (4 + c) : (8 + c);
            uint32_t* Bh = smw + 9216 + (s * 2 + 0) * 2304;
            uint32_t* Bl = smw + 9216 + (s * 2 + 1) * 2304;
            for (int i = t; i < 512; i += 256) {
                int row = i >> 3, seg = i & 7;
                uint4 vh = GB4[((size_t)(2 * layer + 0) * 13 + tile) * 512 + i];
                uint4 vb = GB4[((size_t)(2 * layer + 1) * 13 + tile) * 512 + i];
                *(uint4*)(Bh + row * 36 + seg * 4) = vh;
                *(uint4*)(Bl + row * 36 + seg * 4) = vb;
            }
        }
        __syncthreads();

#pragma unroll 1
        for (int ks = 0; ks < 4; ks++) {
            uint32_t arow = (uint32_t)((w * 16 + ((m & 1) << 3) + rr) * 36 + ks * 8 + ((m >> 1) << 2)) << 2;
            uint32_t ah0, ah1, ah2, ah3, al0, al1, al2, al3;
            ldsm4(ah0, ah1, ah2, ah3, sAh + arow);
            ldsm4(al0, al1, al2, al3, sAl + arow);
#pragma unroll
            for (int s = 0; s < 3; s++) {
                if (s > 0 && c == 0) continue;
                uint32_t bhb = sB0 + (uint32_t)((s * 2 + 0) * 2304 * 4);
                uint32_t blb = sB0 + (uint32_t)((s * 2 + 1) * 2304 * 4);
#pragma unroll
                for (int j = 0; j < 4; j++) {
                    uint32_t boff = (uint32_t)((j * 16 + ((m >> 1) << 3) + rr) * 36 + ks * 8 + ((m & 1) << 2)) << 2;
                    uint32_t b0, b1, b2, b3, c0, c1, c2, c3;
                    ldsm4(b0, b1, b2, b3, bhb + boff);
                    ldsm4(c0, c1, c2, c3, blb + boff);
                    mma16816(d[s][2 * j], ah0, ah1, ah2, ah3, b0, b1);
                    mma16816(d[s][2 * j], al0, al1, al2, al3, b0, b1);
                    mma16816(d[s][2 * j], ah0, ah1, ah2, ah3, c0, c1);
                    mma16816(d[s][2 * j + 1], ah0, ah1, ah2, ah3, b2, b3);
                    mma16816(d[s][2 * j + 1], al0, al1, al2, al3, b2, b3);
                    mma16816(d[s][2 * j + 1], ah0, ah1, ah2, ah3, c2, c3);
                }
            }
        }
    }

    // ---- combine -> F[128][68] (overlaps A areas) ----
    __syncthreads();
    float* F = (float*)smw;
    const float* b13 = g_W13 + layer * 833 * 64 + 832 * 64;
#pragma unroll
    for (int q2 = 0; q2 < 2; q2++) {
        int rl = w * 16 + (lane >> 2) + q2 * 8;
        int node = node0 + rl;
        float amp = (node < NN) ? g_amp[node] : 1.f;
        float ramp = 1.f / amp;
#pragma unroll
        for (int nt = 0; nt < 8; nt++) {
            int col = nt * 8 + (lane & 3) * 2;
            float y0 = d[0][nt][2 * q2] + amp * d[1][nt][2 * q2] + ramp * d[2][nt][2 * q2] + b13[col];
            float y1 = d[0][nt][2 * q2 + 1] + amp * d[1][nt][2 * q2 + 1] + ramp * d[2][nt][2 * q2 + 1] + b13[col + 1];
            F[rl * 68 + col] = fmaxf(y0, 0.f);
            F[rl * 68 + col + 1] = fmaxf(y1, 0.f);
        }
    }
    __syncthreads();

    if (do_ln) {
        uint32_t* pAh = smw + 9216;
        uint32_t* pAl = smw + 13824;
        uint32_t* GAw = (uint32_t*)g_A;
        uint32_t* GAlw = (uint32_t*)g_Al;
        for (int k2 = 0; k2 < 16; k2++) {
            int nl = w * 16 + k2;
            int node = node0 + nl;
            float v0 = F[nl * 68 + 2 * lane], v1 = F[nl * 68 + 2 * lane + 1];
            float s = v0 + v1;
            for (int o = 16; o > 0; o >>= 1) s += __shfl_xor_sync(0xffffffffu, s, o);
            float mu = s * (1.f / 64.f);
            float d0 = v0 - mu, d1 = v1 - mu;
            float q = d0 * d0 + d1 * d1;
            for (int o = 16; o > 0; o >>= 1) q += __shfl_xor_sync(0xffffffffu, q, o);
            float rstd = rsqrtf(q * (1.f / 64.f) + 1e-5f);
            float o0 = d0 * rstd * lnw[2 * lane] + lnb[2 * lane];
            float o1 = d1 * rstd * lnw[2 * lane + 1] + lnb[2 * lane + 1];
            __nv_bfloat16 h0, l0, h1, l1;
            bsplit(o0, h0, l0);
            bsplit(o1, h1, l1);
            uint32_t hw = (uint32_t)bbits(h0) | ((uint32_t)bbits(h1) << 16);
            uint32_t lw2 = (uint32_t)bbits(l0) | ((uint32_t)bbits(l1) << 16);
            pAh[nl * 36 + lane] = hw;
            pAl[nl * 36 + lane] = lw2;
            if (node < NN) {
                GAw[(size_t)node * 160 + lane] = hw;
                GAlw[(size_t)node * 160 + lane] = lw2;
            }
        }
        // stage pre-B for next layer
        int nlayer = layer + 1;
        const uint4* GBp4 = (const uint4*)g_Bp;
        for (int i = t; i < 2048; i += 256) {
            int tidx = i >> 9, r = i & 511;
            uint4 v = GBp4[((size_t)(nlayer * 2 + (tidx >> 1)) * 2 + (tidx & 1)) * 512 + r];
            *(uint4*)(smw + 18432 + tidx * 2304 + (r >> 3) * 36 + (r & 7) * 4) = v;
        }
        __syncthreads();

        // pre mma: ab = h @ [Wa|Wb]
        uint32_t sPh = (uint32_t)__cvta_generic_to_shared(pAh);
        uint32_t sPl = (uint32_t)__cvta_generic_to_shared(pAl);
        uint32_t sPB = (uint32_t)__cvta_generic_to_shared(smw + 18432);
        float dp[2][8][4];
#pragma unroll
        for (int s = 0; s < 2; s++)
#pragma unroll
            for (int nt = 0; nt < 8; nt++)
#pragma unroll
                for (int q = 0; q < 4; q++) dp[s][nt][q] = 0.f;
#pragma unroll 1
        for (int ks = 0; ks < 4; ks++) {
            uint32_t arow = (uint32_t)((w * 16 + ((m & 1) << 3) + rr) * 36 + ks * 8 + ((m >> 1) << 2)) << 2;
            uint32_t ah0, ah1, ah2, ah3, al0, al1, al2, al3;
            ldsm4(ah0, ah1, ah2, ah3, sPh + arow);
            ldsm4(al0, al1, al2, al3, sPl + arow);
#pragma unroll
            for (int s = 0; s < 2; s++) {
                uint32_t bhb = sPB + (uint32_t)(s * 2304 * 4);
                uint32_t blb = sPB + (uint32_t)((2 + s) * 2304 * 4);
#pragma unroll
                for (int j = 0; j < 4; j++) {
                    uint32_t boff = (uint32_t)((j * 16 + ((m >> 1) << 3) + rr) * 36 + ks * 8 + ((m & 1) << 2)) << 2;
                    uint32_t b0, b1, b2, b3, c0, c1, c2, c3;
                    ldsm4(b0, b1, b2, b3, bhb + boff);
                    ldsm4(c0, c1, c2, c3, blb + boff);
                    mma16816(dp[s][2 * j], ah0, ah1, ah2, ah3, b0, b1);
                    mma16816(dp[s][2 * j], al0, al1, al2, al3, b0, b1);
                    mma16816(dp[s][2 * j], ah0, ah1, ah2, ah3, c0, c1);
                    mma16816(dp[s][2 * j + 1], ah0, ah1, ah2, ah3, b2, b3);
                    mma16816(dp[s][2 * j + 1], al0, al1, al2, al3, b2, b3);
                    mma16816(dp[s][2 * j + 1], ah0, ah1, ah2, ah3, c2, c3);
                }
            }
        }
#pragma unroll
        for (int q2 = 0; q2 < 2; q2++) {
            int node = node0 + w * 16 + (lane >> 2) + q2 * 8;
            if (node >= NN) continue;
#pragma unroll
            for (int s = 0; s < 2; s++)
#pragma unroll
                for (int nt = 0; nt < 8; nt++) {
                    int col = nt * 8 + (lane & 3) * 2;
                    float y0 = dp[s][nt][2 * q2], y1 = dp[s][nt][2 * q2 + 1];
                    if (s == 0) { y0 += pbn[col]; y1 += pbn[col + 1]; }
                    *(float2*)(g_ab + (size_t)node * 128 + s * 64 + col) = make_float2(y0, y1);
                }
        }
    } else {
        for (int k2 = 0; k2 < 16; k2++) {
            int nl = w * 16 + k2;
            int node = node0 + nl;
            if (node >= NN) continue;
            int g = batch[node];
            atomicAdd(&g_pool[g * 64 + lane], F[nl * 68 + lane]);
            atomicAdd(&g_pool[g * 64 + 32 + lane], F[nl * 68 + 32 + lane]);
            if (lane == 0) atomicAdd(&g_gcnt[g], 1.f);
        }
    }
}

// ==================== final MLP ====================
__global__ void mlp_kernel(const float* __restrict__ w1, const float* __restrict__ b1,
                           const float* __restrict__ w2, const float* __restrict__ b2,
                           float* __restrict__ out) {
    int g = blockIdx.x, t = threadIdx.x;
    float inv = 1.f / fmaxf(g_gcnt[g], 1.f);
    float acc = b1[t];
    for (int k = 0; k < 64; k++) acc = fmaf(g_pool[g * 64 + k] * inv, w1[k * 32 + t], acc);
    acc = fmaxf(acc, 0.f);
    float p = acc * w2[t];
    for (int o = 16; o > 0; o >>= 1) p += __shfl_xor_sync(0xffffffffu, p, o);
    if (t == 0) out[g] = p + b2[0];
}

// ==================== host ====================
extern "C" void kernel_launch(void* const* d_in, const int* in_sizes, int n_in,
                              void* d_out, int out_size) {
    const float* x      = (const float*)d_in[0];
    const int*   esrc   = (const int*)d_in[1];
    const int*   edst   = (const int*)d_in[2];
    const int*   batch  = (const int*)d_in[3];
    const float* pre_w  = (const float*)d_in[4];
    const float* pre_b  = (const float*)d_in[5];
    const float* post_w = (const float*)d_in[6];
    const float* post_b = (const float*)d_in[7];
    const float* lin_w  = (const float*)d_in[8];
    const float* lin_b  = (const float*)d_in[9];
    const float* ln_w   = (const float*)d_in[10];
    const float* ln_b   = (const float*)d_in[11];
    const float* m1w    = (const float*)d_in[12];
    const float* m1b    = (const float*)d_in[13];
    const float* m2w    = (const float*)d_in[14];
    const float* m2b    = (const float*)d_in[15];
    float* out = (float*)d_out;

    cudaFuncSetAttribute(pre_mma_kernel, cudaFuncAttributeMaxDynamicSharedMemorySize, PRE_SMEM_B);
    cudaFuncSetAttribute(node_mma_kernel, cudaFuncAttributeMaxDynamicSharedMemorySize, NODE_SMEM_B);

    zero_front_kernel<<<(NN + 255) / 256, 256>>>();
    split_x_kernel<<<(NN * 64 + 255) / 256, 256>>>(x);
    fold_all_kernel<<<(3 * 833 * 64 + 255) / 256, 256>>>(post_w, post_b, lin_w, lin_b);
    pack_all_kernel<<<(3 * 13 * 4096 + 3 * 2 * 4096 + 255) / 256, 256>>>(pre_w);
    hist_kernel<<<(NE + 255) / 256, 256>>>(edst);
    scan1_kernel<<<NBLK_SCAN, 256>>>();
    scan2_kernel<<<1, 256>>>();
    scan3_kernel<<<NBLK_SCAN, 256>>>();
    scatter_kernel<<<(NE + 255) / 256, 256>>>(edst, esrc);

    const int NB = (NN + 63) / 64;     // 782 (pre_mma)
    const int MB = (NN + 127) / 128;   // 391 (node_mma)
    const int WB = (NN * 32 + 255) / 256;

    pre_mma_kernel<<<NB, 256, PRE_SMEM_B>>>(0, pre_b);
    for (int i = 0; i < 3; i++) {
        agg_kernel<<<WB, 256>>>();
        node_mma_kernel<<<MB, 256, NODE_SMEM_B>>>(i, i < 2, ln_w + i * 64, ln_b + i * 64,
                                                  batch, pre_b + (i + 1 < 3 ? (i + 1) : 0) * 64);
    }
    mlp_kernel<<<NG, 32>>>(m1w, m1b, m2w, m2b, out);
}

// round 13
// speedup vs baseline: 1.3081x; 1.3081x over previous
#include <cuda_runtime.h>
#include <cuda_bf16.h>
#include <cstdint>

#define NN 50000
#define NE 800000
#define NG 500
#define NBLK_SCAN 196   // ceil(NN/256)

// ==================== device scratch ====================
__device__ float g_ab[NN * 128];
__device__ float g_amp[NN];
__device__ int   g_hist[NN];
__device__ int   g_rowptr[NN + 1];
__device__ int   g_woff[NN];
__device__ int   g_bsum[256];
__device__ int   g_srcs[NE];
__device__ float g_W13[3 * 833 * 64];              // [layer][k<=832][j]; k=832 -> b13
__device__ __nv_bfloat16 g_A[(size_t)NN * 320];    // [node][5*64] hi: h|mean|mx|mn|std
__device__ __nv_bfloat16 g_Al[(size_t)NN * 320];   // lo
__device__ __nv_bfloat16 g_B[3 * 2 * 13 * 4096];   // [layer][part][tile][j][k]
__device__ __nv_bfloat16 g_Bp[3 * 2 * 2 * 4096];   // [layer][part][tile][j][k]
__device__ float g_pool[NG * 64];
__device__ float g_gcnt[NG];

__device__ __forceinline__ void bsplit(float v, __nv_bfloat16& h, __nv_bfloat16& l) {
    h = __float2bfloat16(v);
    l = __float2bfloat16(v - __bfloat162float(h));
}
__device__ __forceinline__ uint16_t bbits(__nv_bfloat16 h) {
    return *reinterpret_cast<uint16_t*>(&h);
}

// ==================== setup ====================
__global__ void zero_front_kernel() {
    int i = blockIdx.x * blockDim.x + threadIdx.x;
    if (i < NN) g_hist[i] = 0;
    if (i < NG * 64) g_pool[i] = 0.f;
    if (i < NG) g_gcnt[i] = 0.f;
}
__global__ void split_x_kernel(const float* __restrict__ x) {
    int i = blockIdx.x * blockDim.x + threadIdx.x;
    if (i < NN * 64) {
        int n = i >> 6, c = i & 63;
        __nv_bfloat16 h, l;
        bsplit(x[i], h, l);
        g_A[(size_t)n * 320 + c] = h;
        g_Al[(size_t)n * 320 + c] = l;
    }
}

// ==================== weight prep (all 3 layers up front) ====================
__global__ void fold_all_kernel(const float* __restrict__ post_w, const float* __restrict__ post_b,
                                const float* __restrict__ lin_w, const float* __restrict__ lin_b) {
    int idx = blockIdx.x * blockDim.x + threadIdx.x;
    if (idx >= 3 * 833 * 64) return;
    int layer = idx / (833 * 64);
    int r = idx % (833 * 64);
    int k = r >> 6, j = r & 63;
    const float* ow = post_w + layer * 832 * 64;
    const float* lw = lin_w + layer * 64 * 64;
    if (k < 832) {
        float s = 0.f;
        for (int c = 0; c < 64; c++) s = fmaf(ow[k * 64 + c], lw[c * 64 + j], s);
        g_W13[idx] = s;
    } else {
        float s = lin_b[layer * 64 + j];
        for (int c = 0; c < 64; c++) s = fmaf(post_b[layer * 64 + c], lw[c * 64 + j], s);
        g_W13[idx] = s;  // b13 slot (k==832)
    }
}
__global__ void pack_all_kernel(const float* __restrict__ pre_w) {
    int idx = blockIdx.x * blockDim.x + threadIdx.x;
    if (idx < 3 * 13 * 4096) {
        int layer = idx / (13 * 4096);
        int r = idx % (13 * 4096);
        int tile = r >> 12, q = r & 4095;
        int j = q >> 6, k = q & 63;
        float w = g_W13[layer * 833 * 64 + (tile * 64 + k) * 64 + j];
        __nv_bfloat16 h, l;
        bsplit(w, h, l);
        g_B[((size_t)(layer * 2 + 0) * 13 + tile) * 4096 + q] = h;
        g_B[((size_t)(layer * 2 + 1) * 13 + tile) * 4096 + q] = l;
    } else if (idx < 3 * 13 * 4096 + 3 * 2 * 4096) {
        int i2 = idx - 3 * 13 * 4096;
        int layer = i2 / (2 * 4096);
        int r = i2 % (2 * 4096);
        int tile = r >> 12, q = r & 4095;
        int j = q >> 6, k = q & 63;
        float w = pre_w[layer * 128 * 64 + (tile * 64 + k) * 64 + j];
        __nv_bfloat16 h, l;
        bsplit(w, h, l);
        g_Bp[((size_t)(layer * 2 + 0) * 2 + tile) * 4096 + q] = h;
        g_Bp[((size_t)(layer * 2 + 1) * 2 + tile) * 4096 + q] = l;
    }
}

// ==================== CSR build ====================
__global__ void hist_kernel(const int* __restrict__ dst) {
    int e = blockIdx.x * blockDim.x + threadIdx.x;
    if (e < NE) atomicAdd(&g_hist[dst[e]], 1);
}
__global__ void scan1_kernel() {
    int b = blockIdx.x, t = threadIdx.x, i = b * 256 + t;
    int v = (i < NN) ? g_hist[i] : 0;
    int s = v;
#pragma unroll
    for (int o = 1; o < 32; o <<= 1) {
        int u = __shfl_up_sync(0xffffffffu, s, o);
        if ((t & 31) >= o) s += u;
    }
    __shared__ int wsum[8];
    if ((t & 31) == 31) wsum[t >> 5] = s;
    __syncthreads();
    if (t < 32) {
        int ws_ = (t < 8) ? wsum[t] : 0;
#pragma unroll
        for (int o = 1; o < 8; o <<= 1) {
            int u = __shfl_up_sync(0xffffffffu, ws_, o);
            if (t >= o) ws_ += u;
        }
        if (t < 8) wsum[t] = ws_;
    }
    __syncthreads();
    int incl = s + ((t >= 32) ? wsum[(t >> 5) - 1] : 0);
    if (i < NN) g_rowptr[i] = incl - v;
    if (t == 255) g_bsum[b] = incl;
}
__global__ void scan2_kernel() {
    int t = threadIdx.x;
    int v = (t < NBLK_SCAN) ? g_bsum[t] : 0;
    int s = v;
#pragma unroll
    for (int o = 1; o < 32; o <<= 1) {
        int u = __shfl_up_sync(0xffffffffu, s, o);
        if ((t & 31) >= o) s += u;
    }
    __shared__ int wsum[8];
    if ((t & 31) == 31) wsum[t >> 5] = s;
    __syncthreads();
    if (t < 32) {
        int ws_ = (t < 8) ? wsum[t] : 0;
#pragma unroll
        for (int o = 1; o < 8; o <<= 1) {
            int u = __shfl_up_sync(0xffffffffu, ws_, o);
            if (t >= o) ws_ += u;
        }
        if (t < 8) wsum[t] = ws_;
    }
    __syncthreads();
    int incl = s + ((t >= 32) ? wsum[(t >> 5) - 1] : 0);
    if (t < NBLK_SCAN) g_bsum[t] = incl - v;
    if (t == 0) g_rowptr[NN] = NE;
}
__global__ void scan3_kernel() {
    int i = blockIdx.x * 256 + threadIdx.x;
    if (i < NN) {
        int r = g_rowptr[i] + g_bsum[blockIdx.x];
        g_rowptr[i] = r;
        g_woff[i] = r;
        float degc = fmaxf((float)g_hist[i], 1.f);
        g_amp[i] = logf(degc + 1.f) * 0.35295612f;
    }
}
__global__ void scatter_kernel(const int* __restrict__ dst, const int* __restrict__ src) {
    int e = blockIdx.x * blockDim.x + threadIdx.x;
    if (e < NE) {
        int d = dst[e];
        int pos = atomicAdd(&g_woff[d], 1);
        g_srcs[pos] = src[e];
    }
}

// ==================== mma helpers ====================
__device__ __forceinline__ void mma16816(float* d, uint32_t a0, uint32_t a1, uint32_t a2,
                                         uint32_t a3, uint32_t b0, uint32_t b1) {
    asm("mma.sync.aligned.m16n8k16.row.col.f32.bf16.bf16.f32 "
        "{%0,%1,%2,%3}, {%4,%5,%6,%7}, {%8,%9}, {%0,%1,%2,%3};"
        : "+f"(d[0]), "+f"(d[1]), "+f"(d[2]), "+f"(d[3])
        : "r"(a0), "r"(a1), "r"(a2), "r"(a3), "r"(b0), "r"(b1));
}
__device__ __forceinline__ void ldsm4(uint32_t& r0, uint32_t& r1, uint32_t& r2, uint32_t& r3,
                                      uint32_t saddr) {
    asm volatile("ldmatrix.sync.aligned.m8n8.x4.shared.b16 {%0,%1,%2,%3}, [%4];"
                 : "=r"(r0), "=r"(r1), "=r"(r2), "=r"(r3) : "r"(saddr));
}

// ==================== pre-GEMM via mma.sync (proven LDS path) ====================
#define PRE_SMEM_B (2304 * 6 * 4)
__global__ void __launch_bounds__(256)
pre_mma_kernel(int layer, const float* __restrict__ pb) {
    extern __shared__ uint32_t smw[];
    uint32_t* Ah = smw;
    uint32_t* Alo = smw + 2304;
    int t = threadIdx.x, lane = t & 31, w = t >> 5;
    int ws = w >> 1, wc = w & 1;
    int node0 = blockIdx.x * 64;
    const uint4* GA4 = (const uint4*)g_A;
    const uint4* GAl4 = (const uint4*)g_Al;
    const uint4* GBp4 = (const uint4*)g_Bp;

    for (int i = t; i < 512; i += 256) {
        int row = i >> 3, seg = i & 7;
        int n = node0 + row;
        if (n > NN - 1) n = NN - 1;
        uint4 va = GA4[(size_t)n * 40 + seg];
        uint4 vl = GAl4[(size_t)n * 40 + seg];
        *(uint4*)(Ah + row * 36 + seg * 4) = va;
        *(uint4*)(Alo + row * 36 + seg * 4) = vl;
    }
    for (int i = t; i < 2048; i += 256) {
        int tidx = i >> 9, r = i & 511;
        int row = r >> 3, seg = r & 7;
        uint4 v = GBp4[((size_t)(layer * 2 + (tidx >> 1)) * 2 + (tidx & 1)) * 512 + r];
        *(uint4*)(smw + 4608 + tidx * 2304 + row * 36 + seg * 4) = v;
    }
    __syncthreads();

    float d[2][4][4];
#pragma unroll
    for (int s = 0; s < 2; s++)
#pragma unroll
        for (int nt = 0; nt < 4; nt++)
#pragma unroll
            for (int q = 0; q < 4; q++) d[s][nt][q] = 0.f;

    int ra = ws * 16 + (lane >> 2);
#pragma unroll 1
    for (int ks = 0; ks < 4; ks++) {
        int kw = ks * 8 + (lane & 3);
        uint32_t ah0 = Ah[ra * 36 + kw],      ah1 = Ah[(ra + 8) * 36 + kw];
        uint32_t ah2 = Ah[ra * 36 + kw + 4],  ah3 = Ah[(ra + 8) * 36 + kw + 4];
        uint32_t al0 = Alo[ra * 36 + kw],     al1 = Alo[(ra + 8) * 36 + kw];
        uint32_t al2 = Alo[ra * 36 + kw + 4], al3 = Alo[(ra + 8) * 36 + kw + 4];
#pragma unroll
        for (int s = 0; s < 2; s++) {
            const uint32_t* Bh = smw + 4608 + s * 2304;
            const uint32_t* Bl = smw + 4608 + (2 + s) * 2304;
#pragma unroll
            for (int nt = 0; nt < 4; nt++) {
                int bi = (wc * 32 + nt * 8 + (lane >> 2)) * 36 + kw;
                uint32_t bh0 = Bh[bi], bh1 = Bh[bi + 4];
                uint32_t bl0 = Bl[bi], bl1 = Bl[bi + 4];
                mma16816(d[s][nt], ah0, ah1, ah2, ah3, bh0, bh1);
                mma16816(d[s][nt], al0, al1, al2, al3, bh0, bh1);
                mma16816(d[s][nt], ah0, ah1, ah2, ah3, bl0, bl1);
            }
        }
    }
#pragma unroll
    for (int half = 0; half < 2; half++) {
        int node = node0 + ra + half * 8;
        if (node >= NN) continue;
#pragma unroll
        for (int s = 0; s < 2; s++)
#pragma unroll
            for (int nt = 0; nt < 4; nt++) {
                int col = wc * 32 + nt * 8 + (lane & 3) * 2;
                float y0 = d[s][nt][2 * half], y1 = d[s][nt][2 * half + 1];
                if (s == 0) { y0 += pb[col]; y1 += pb[col + 1]; }
                *(float2*)(g_ab + (size_t)node * 128 + s * 64 + col) = make_float2(y0, y1);
            }
    }
}

// ==================== aggregation: 2 edges/iter via LDG.128 ====================
__global__ void agg_kernel() {
    int n = (blockIdx.x * blockDim.x + threadIdx.x) >> 5;
    if (n >= NN) return;
    int lane = threadIdx.x & 31;
    int half = lane >> 4, hl = lane & 15;
    int s0 = g_rowptr[n], s1 = g_rowptr[n + 1];
    int deg = s1 - s0;
    float S1[4] = {0.f, 0.f, 0.f, 0.f}, S2[4] = {0.f, 0.f, 0.f, 0.f};
    float MX[4] = {-3.4e38f, -3.4e38f, -3.4e38f, -3.4e38f};
    float MN[4] = {3.4e38f, 3.4e38f, 3.4e38f, 3.4e38f};
    for (int e = s0 + half; e < s1; e += 2) {
        int src = g_srcs[e];
        float4 v = *(const float4*)(g_ab + (size_t)src * 128 + 64 + hl * 4);
        S1[0] += v.x; S2[0] = fmaf(v.x, v.x, S2[0]); MX[0] = fmaxf(MX[0], v.x); MN[0] = fminf(MN[0], v.x);
        S1[1] += v.y; S2[1] = fmaf(v.y, v.y, S2[1]); MX[1] = fmaxf(MX[1], v.y); MN[1] = fminf(MN[1], v.y);
        S1[2] += v.z; S2[2] = fmaf(v.z, v.z, S2[2]); MX[2] = fmaxf(MX[2], v.z); MN[2] = fminf(MN[2], v.z);
        S1[3] += v.w; S2[3] = fmaf(v.w, v.w, S2[3]); MX[3] = fmaxf(MX[3], v.w); MN[3] = fminf(MN[3], v.w);
    }
#pragma unroll
    for (int q = 0; q < 4; q++) {
        S1[q] += __shfl_xor_sync(0xffffffffu, S1[q], 16);
        S2[q] += __shfl_xor_sync(0xffffffffu, S2[q], 16);
        MX[q] = fmaxf(MX[q], __shfl_xor_sync(0xffffffffu, MX[q], 16));
        MN[q] = fminf(MN[q], __shfl_xor_sync(0xffffffffu, MN[q], 16));
    }
    float4 av = *(const float4*)(g_ab + (size_t)n * 128 + hl * 4);
    float a[4] = {av.x, av.y, av.z, av.w};
    float degf = (float)deg, degc = fmaxf(degf, 1.f), rdeg = 1.f / degc;
    size_t base = (size_t)n * 320;
#pragma unroll
    for (int which = 0; which < 2; which++) {
        float v[4];
        int s;
        if (half == 0) {
            if (which == 0) {
                s = 0;
#pragma unroll
                for (int q = 0; q < 4; q++) v[q] = (degf * a[q] + S1[q]) * rdeg;
            } else {
                s = 1;
#pragma unroll
                for (int q = 0; q < 4; q++) v[q] = (deg > 0) ? a[q] + MX[q] : 0.f;
            }
        } else {
            if (which == 0) {
                s = 2;
#pragma unroll
                for (int q = 0; q < 4; q++) v[q] = (deg > 0) ? a[q] + MN[q] : 0.f;
            } else {
                s = 3;
#pragma unroll
                for (int q = 0; q < 4; q++) {
                    float mean = (degf * a[q] + S1[q]) * rdeg;
                    float msq = (degf * a[q] * a[q] + 2.f * a[q] * S1[q] + S2[q]) * rdeg;
                    v[q] = sqrtf(fmaxf(msq - mean * mean, 0.f) + 1e-5f);
                }
            }
        }
        uint32_t hu0, hu1, lu0, lu1;
        __nv_bfloat16 hh, ll;
        bsplit(v[0], hh, ll); hu0 = bbits(hh); lu0 = bbits(ll);
        bsplit(v[1], hh, ll); hu0 |= (uint32_t)bbits(hh) << 16; lu0 |= (uint32_t)bbits(ll) << 16;
        bsplit(v[2], hh, ll); hu1 = bbits(hh); lu1 = bbits(ll);
        bsplit(v[3], hh, ll); hu1 |= (uint32_t)bbits(hh) << 16; lu1 |= (uint32_t)bbits(ll) << 16;
        size_t o = base + (size_t)(1 + s) * 64 + hl * 4;
        *(uint2*)(g_A + o) = make_uint2(hu0, hu1);
        *(uint2*)(g_Al + o) = make_uint2(lu0, lu1);
    }
}

// ==================== node GEMM (ldmatrix, M=64) + fused LN / pool epilogue ====
#define NODE_SMEM_W 18432
#define NODE_SMEM_B (NODE_SMEM_W * 4)

__global__ void __launch_bounds__(256)
node_mma_kernel(int layer, int do_ln, const float* __restrict__ lnw,
                const float* __restrict__ lnb, const int* __restrict__ batch) {
    extern __shared__ uint32_t smw[];
    uint32_t* Ah = smw;
    uint32_t* Alo = smw + 2304;
    int t = threadIdx.x, lane = t & 31, w = t >> 5;
    int ws = w >> 1, wc = w & 1;
    int node0 = blockIdx.x * 64;

    float d[3][4][4];
#pragma unroll
    for (int s = 0; s < 3; s++)
#pragma unroll
        for (int nt = 0; nt < 4; nt++)
#pragma unroll
            for (int q = 0; q < 4; q++) d[s][nt][q] = 0.f;

    const uint4* GA4 = (const uint4*)g_A;
    const uint4* GAl4 = (const uint4*)g_Al;
    const uint4* GB4 = (const uint4*)g_B;

    uint32_t sAh = (uint32_t)__cvta_generic_to_shared(Ah);
    uint32_t sAl = (uint32_t)__cvta_generic_to_shared(Alo);
    uint32_t sB0 = (uint32_t)__cvta_generic_to_shared(smw + 4608);

    int m = lane >> 3, rr = lane & 7;
    int ra = ws * 16 + (lane >> 2);

    for (int c = 0; c < 5; c++) {
        __syncthreads();
        for (int i = t; i < 512; i += 256) {
            int row = i >> 3, seg = i & 7;
            int n = node0 + row;
            if (n > NN - 1) n = NN - 1;
            uint4 va = GA4[(size_t)n * 40 + c * 8 + seg];
            uint4 vl = GAl4[(size_t)n * 40 + c * 8 + seg];
            *(uint4*)(Ah + row * 36 + seg * 4) = va;
            *(uint4*)(Alo + row * 36 + seg * 4) = vl;
        }
        int nsets = (c == 0) ? 1 : 3;
        for (int s = 0; s < nsets; s++) {
            int tile = (s == 0) ? c : (s == 1) ? (4 + c) : (8 + c);
            uint32_t* Bh = smw + 4608 + (s * 2 + 0) * 2304;
            uint32_t* Bl = smw + 4608 + (s * 2 + 1) * 2304;
            for (int i = t; i < 512; i += 256) {
                int row = i >> 3, seg = i & 7;
                uint4 vh = GB4[((size_t)(2 * layer + 0) * 13 + tile) * 512 + i];
                uint4 vb = GB4[((size_t)(2 * layer + 1) * 13 + tile) * 512 + i];
                *(uint4*)(Bh + row * 36 + seg * 4) = vh;
                *(uint4*)(Bl + row * 36 + seg * 4) = vb;
            }
        }
        __syncthreads();

#pragma unroll 1
        for (int ks = 0; ks < 4; ks++) {
            uint32_t arow = (uint32_t)((ws * 16 + ((m & 1) << 3) + rr) * 36 + ks * 8 + ((m >> 1) << 2)) << 2;
            uint32_t ah0, ah1, ah2, ah3, al0, al1, al2, al3;
            ldsm4(ah0, ah1, ah2, ah3, sAh + arow);
            ldsm4(al0, al1, al2, al3, sAl + arow);
            uint32_t brow = (uint32_t)((wc * 32 + ((m >> 1) << 3) + rr) * 36 + ks * 8 + ((m & 1) << 2)) << 2;
            uint32_t brow2 = brow + (uint32_t)(16 * 36 * 4);
#pragma unroll
            for (int s = 0; s < 3; s++) {
                if (s > 0 && c == 0) continue;
                uint32_t bhb = sB0 + (uint32_t)((s * 2 + 0) * 2304 * 4);
                uint32_t blb = sB0 + (uint32_t)((s * 2 + 1) * 2304 * 4);
                uint32_t b0, b1, b2, b3, c0, c1, c2, c3;
                ldsm4(b0, b1, b2, b3, bhb + brow);
                ldsm4(c0, c1, c2, c3, blb + brow);
                mma16816(d[s][0], ah0, ah1, ah2, ah3, b0, b1);
                mma16816(d[s][0], al0, al1, al2, al3, b0, b1);
                mma16816(d[s][0], ah0, ah1, ah2, ah3, c0, c1);
                mma16816(d[s][1], ah0, ah1, ah2, ah3, b2, b3);
                mma16816(d[s][1], al0, al1, al2, al3, b2, b3);
                mma16816(d[s][1], ah0, ah1, ah2, ah3, c2, c3);
                ldsm4(b0, b1, b2, b3, bhb + brow2);
                ldsm4(c0, c1, c2, c3, blb + brow2);
                mma16816(d[s][2], ah0, ah1, ah2, ah3, b0, b1);
                mma16816(d[s][2], al0, al1, al2, al3, b0, b1);
                mma16816(d[s][2], ah0, ah1, ah2, ah3, c0, c1);
                mma16816(d[s][3], ah0, ah1, ah2, ah3, b2, b3);
                mma16816(d[s][3], al0, al1, al2, al3, b2, b3);
                mma16816(d[s][3], ah0, ah1, ah2, ah3, c2, c3);
            }
        }
    }

    // ---- epilogue: combine -> smem tile F[64][68] ----
    __syncthreads();
    float* F = (float*)smw;
    const float* b13 = g_W13 + layer * 833 * 64 + 832 * 64;
#pragma unroll
    for (int half = 0; half < 2; half++) {
        int node_local = ra + half * 8;
        int node = node0 + node_local;
        float amp = (node < NN) ? g_amp[node] : 1.f;
        float ramp = 1.f / amp;
#pragma unroll
        for (int nt = 0; nt < 4; nt++) {
            int col = wc * 32 + nt * 8 + (lane & 3) * 2;
            float y0 = d[0][nt][2 * half] + amp * d[1][nt][2 * half]
                     + ramp * d[2][nt][2 * half] + b13[col];
            float y1 = d[0][nt][2 * half + 1] + amp * d[1][nt][2 * half + 1]
                     + ramp * d[2][nt][2 * half + 1] + b13[col + 1];
            F[node_local * 68 + col] = fmaxf(y0, 0.f);
            F[node_local * 68 + col + 1] = fmaxf(y1, 0.f);
        }
    }
    __syncthreads();

    // ---- per-node LN (layers 0,1) or pool (layer 2); warp w owns nodes w*8..w*8+7 ----
    for (int k2 = 0; k2 < 8; k2++) {
        int nl = w * 8 + k2;
        int node = node0 + nl;
        if (node >= NN) continue;
        float v0 = F[nl * 68 + lane], v1 = F[nl * 68 + 32 + lane];
        if (do_ln) {
            float s = v0 + v1;
            for (int o = 16; o > 0; o >>= 1) s += __shfl_xor_sync(0xffffffffu, s, o);
            float mu = s * (1.f / 64.f);
            float d0 = v0 - mu, d1 = v1 - mu;
            float q = d0 * d0 + d1 * d1;
            for (int o = 16; o > 0; o >>= 1) q += __shfl_xor_sync(0xffffffffu, q, o);
            float rstd = rsqrtf(q * (1.f / 64.f) + 1e-5f);
            float o0 = d0 * rstd * lnw[lane] + lnb[lane];
            float o1 = d1 * rstd * lnw[32 + lane] + lnb[32 + lane];
            __nv_bfloat16 h, l;
            bsplit(o0, h, l);
            g_A[(size_t)node * 320 + lane] = h; g_Al[(size_t)node * 320 + lane] = l;
            bsplit(o1, h, l);
            g_A[(size_t)node * 320 + 32 + lane] = h; g_Al[(size_t)node * 320 + 32 + lane] = l;
        } else {
            int g = batch[node];
            atomicAdd(&g_pool[g * 64 + lane], v0);
            atomicAdd(&g_pool[g * 64 + 32 + lane], v1);
            if (lane == 0) atomicAdd(&g_gcnt[g], 1.f);
        }
    }
}

// ==================== final MLP ====================
__global__ void mlp_kernel(const float* __restrict__ w1, const float* __restrict__ b1,
                           const float* __restrict__ w2, const float* __restrict__ b2,
                           float* __restrict__ out) {
    int g = blockIdx.x, t = threadIdx.x;
    float inv = 1.f / fmaxf(g_gcnt[g], 1.f);
    float acc = b1[t];
    for (int k = 0; k < 64; k++) acc = fmaf(g_pool[g * 64 + k] * inv, w1[k * 32 + t], acc);
    acc = fmaxf(acc, 0.f);
    float p = acc * w2[t];
    for (int o = 16; o > 0; o >>= 1) p += __shfl_xor_sync(0xffffffffu, p, o);
    if (t == 0) out[g] = p + b2[0];
}

// ==================== host ====================
extern "C" void kernel_launch(void* const* d_in, const int* in_sizes, int n_in,
                              void* d_out, int out_size) {
    const float* x      = (const float*)d_in[0];
    const int*   esrc   = (const int*)d_in[1];
    const int*   edst   = (const int*)d_in[2];
    const int*   batch  = (const int*)d_in[3];
    const float* pre_w  = (const float*)d_in[4];
    const float* pre_b  = (const float*)d_in[5];
    const float* post_w = (const float*)d_in[6];
    const float* post_b = (const float*)d_in[7];
    const float* lin_w  = (const float*)d_in[8];
    const float* lin_b  = (const float*)d_in[9];
    const float* ln_w   = (const float*)d_in[10];
    const float* ln_b   = (const float*)d_in[11];
    const float* m1w    = (const float*)d_in[12];
    const float* m1b    = (const float*)d_in[13];
    const float* m2w    = (const float*)d_in[14];
    const float* m2b    = (const float*)d_in[15];
    float* out = (float*)d_out;

    cudaFuncSetAttribute(pre_mma_kernel, cudaFuncAttributeMaxDynamicSharedMemorySize, PRE_SMEM_B);
    cudaFuncSetAttribute(node_mma_kernel, cudaFuncAttributeMaxDynamicSharedMemorySize, NODE_SMEM_B);

    zero_front_kernel<<<(NN + 255) / 256, 256>>>();
    split_x_kernel<<<(NN * 64 + 255) / 256, 256>>>(x);
    fold_all_kernel<<<(3 * 833 * 64 + 255) / 256, 256>>>(post_w, post_b, lin_w, lin_b);
    pack_all_kernel<<<(3 * 13 * 4096 + 3 * 2 * 4096 + 255) / 256, 256>>>(pre_w);
    hist_kernel<<<(NE + 255) / 256, 256>>>(edst);
    scan1_kernel<<<NBLK_SCAN, 256>>>();
    scan2_kernel<<<1, 256>>>();
    scan3_kernel<<<NBLK_SCAN, 256>>>();
    scatter_kernel<<<(NE + 255) / 256, 256>>>(edst, esrc);

    const int NB = (NN + 63) / 64;         // 782
    const int WB = (NN * 32 + 255) / 256;  // 6250

    for (int i = 0; i < 3; i++) {
        pre_mma_kernel<<<NB, 256, PRE_SMEM_B>>>(i, pre_b + i * 64);
        agg_kernel<<<WB, 256>>>();
        node_mma_kernel<<<NB, 256, NODE_SMEM_B>>>(i, i < 2, ln_w + i * 64, ln_b + i * 64, batch);
    }
    mlp_kernel<<<NG, 32>>>(m1w, m1b, m2w, m2b, out);
}

// round 14
// speedup vs baseline: 1.3085x; 1.0003x over previous
#include <cuda_runtime.h>
#include <cuda_bf16.h>
#include <cstdint>

#define NN 50000
#define NE 800000
#define NG 500
#define NBLK_SCAN 196   // ceil(NN/256)

// ==================== device scratch ====================
__device__ float g_ab[NN * 128];
__device__ float g_amp[NN];
__device__ int   g_hist[NN];
__device__ int   g_rowptr[NN + 1];
__device__ int   g_woff[NN];
__device__ int   g_bsum[256];
__device__ int   g_srcs[NE];
__device__ float g_W13[3 * 833 * 64];              // [layer][k<=832][j]; k=832 -> b13
__device__ __nv_bfloat16 g_A[(size_t)NN * 320];    // [node][5*64] hi: h|mean|mx|mn|std
__device__ __nv_bfloat16 g_Al[(size_t)NN * 320];   // lo
__device__ __nv_bfloat16 g_B[3 * 2 * 13 * 4096];   // [layer][part][tile][j][k]
__device__ __nv_bfloat16 g_Bp[3 * 2 * 2 * 4096];   // [layer][part][tile][j][k]
__device__ float g_pool[NG * 64];
__device__ float g_gcnt[NG];

__device__ __forceinline__ void bsplit(float v, __nv_bfloat16& h, __nv_bfloat16& l) {
    h = __float2bfloat16(v);
    l = __float2bfloat16(v - __bfloat162float(h));
}
__device__ __forceinline__ uint16_t bbits(__nv_bfloat16 h) {
    return *reinterpret_cast<uint16_t*>(&h);
}

// ==================== setup ====================
__global__ void zero_front_kernel() {
    int i = blockIdx.x * blockDim.x + threadIdx.x;
    if (i < NN) g_hist[i] = 0;
    if (i < NG * 64) g_pool[i] = 0.f;
    if (i < NG) g_gcnt[i] = 0.f;
}
__global__ void split_x_kernel(const float* __restrict__ x) {
    int i = blockIdx.x * blockDim.x + threadIdx.x;
    if (i < NN * 64) {
        int n = i >> 6, c = i & 63;
        __nv_bfloat16 h, l;
        bsplit(x[i], h, l);
        g_A[(size_t)n * 320 + c] = h;
        g_Al[(size_t)n * 320 + c] = l;
    }
}

// ==================== weight prep (all 3 layers up front) ====================
__global__ void fold_all_kernel(const float* __restrict__ post_w, const float* __restrict__ post_b,
                                const float* __restrict__ lin_w, const float* __restrict__ lin_b) {
    int idx = blockIdx.x * blockDim.x + threadIdx.x;
    if (idx >= 3 * 833 * 64) return;
    int layer = idx / (833 * 64);
    int r = idx % (833 * 64);
    int k = r >> 6, j = r & 63;
    const float* ow = post_w + layer * 832 * 64;
    const float* lw = lin_w + layer * 64 * 64;
    if (k < 832) {
        float s = 0.f;
        for (int c = 0; c < 64; c++) s = fmaf(ow[k * 64 + c], lw[c * 64 + j], s);
        g_W13[idx] = s;
    } else {
        float s = lin_b[layer * 64 + j];
        for (int c = 0; c < 64; c++) s = fmaf(post_b[layer * 64 + c], lw[c * 64 + j], s);
        g_W13[idx] = s;  // b13 slot (k==832)
    }
}
__global__ void pack_all_kernel(const float* __restrict__ pre_w) {
    int idx = blockIdx.x * blockDim.x + threadIdx.x;
    if (idx < 3 * 13 * 4096) {
        int layer = idx / (13 * 4096);
        int r = idx % (13 * 4096);
        int tile = r >> 12, q = r & 4095;
        int j = q >> 6, k = q & 63;
        float w = g_W13[layer * 833 * 64 + (tile * 64 + k) * 64 + j];
        __nv_bfloat16 h, l;
        bsplit(w, h, l);
        g_B[((size_t)(layer * 2 + 0) * 13 + tile) * 4096 + q] = h;
        g_B[((size_t)(layer * 2 + 1) * 13 + tile) * 4096 + q] = l;
    } else if (idx < 3 * 13 * 4096 + 3 * 2 * 4096) {
        int i2 = idx - 3 * 13 * 4096;
        int layer = i2 / (2 * 4096);
        int r = i2 % (2 * 4096);
        int tile = r >> 12, q = r & 4095;
        int j = q >> 6, k = q & 63;
        float w = pre_w[layer * 128 * 64 + (tile * 64 + k) * 64 + j];
        __nv_bfloat16 h, l;
        bsplit(w, h, l);
        g_Bp[((size_t)(layer * 2 + 0) * 2 + tile) * 4096 + q] = h;
        g_Bp[((size_t)(layer * 2 + 1) * 2 + tile) * 4096 + q] = l;
    }
}

// ==================== CSR build ====================
__global__ void hist_kernel(const int* __restrict__ dst) {
    int e = blockIdx.x * blockDim.x + threadIdx.x;
    if (e < NE) atomicAdd(&g_hist[dst[e]], 1);
}
__global__ void scan1_kernel() {
    int b = blockIdx.x, t = threadIdx.x, i = b * 256 + t;
    int v = (i < NN) ? g_hist[i] : 0;
    int s = v;
#pragma unroll
    for (int o = 1; o < 32; o <<= 1) {
        int u = __shfl_up_sync(0xffffffffu, s, o);
        if ((t & 31) >= o) s += u;
    }
    __shared__ int wsum[8];
    if ((t & 31) == 31) wsum[t >> 5] = s;
    __syncthreads();
    if (t < 32) {
        int ws_ = (t < 8) ? wsum[t] : 0;
#pragma unroll
        for (int o = 1; o < 8; o <<= 1) {
            int u = __shfl_up_sync(0xffffffffu, ws_, o);
            if (t >= o) ws_ += u;
        }
        if (t < 8) wsum[t] = ws_;
    }
    __syncthreads();
    int incl = s + ((t >= 32) ? wsum[(t >> 5) - 1] : 0);
    if (i < NN) g_rowptr[i] = incl - v;
    if (t == 255) g_bsum[b] = incl;
}
__global__ void scan2_kernel() {
    int t = threadIdx.x;
    int v = (t < NBLK_SCAN) ? g_bsum[t] : 0;
    int s = v;
#pragma unroll
    for (int o = 1; o < 32; o <<= 1) {
        int u = __shfl_up_sync(0xffffffffu, s, o);
        if ((t & 31) >= o) s += u;
    }
    __shared__ int wsum[8];
    if ((t & 31) == 31) wsum[t >> 5] = s;
    __syncthreads();
    if (t < 32) {
        int ws_ = (t < 8) ? wsum[t] : 0;
#pragma unroll
        for (int o = 1; o < 8; o <<= 1) {
            int u = __shfl_up_sync(0xffffffffu, ws_, o);
            if (t >= o) ws_ += u;
        }
        if (t < 8) wsum[t] = ws_;
    }
    __syncthreads();
    int incl = s + ((t >= 32) ? wsum[(t >> 5) - 1] : 0);
    if (t < NBLK_SCAN) g_bsum[t] = incl - v;
    if (t == 0) g_rowptr[NN] = NE;
}
__global__ void scan3_kernel() {
    int i = blockIdx.x * 256 + threadIdx.x;
    if (i < NN) {
        int r = g_rowptr[i] + g_bsum[blockIdx.x];
        g_rowptr[i] = r;
        g_woff[i] = r;
        float degc = fmaxf((float)g_hist[i], 1.f);
        g_amp[i] = logf(degc + 1.f) * 0.35295612f;
    }
}
__global__ void scatter_kernel(const int* __restrict__ dst, const int* __restrict__ src) {
    int e = blockIdx.x * blockDim.x + threadIdx.x;
    if (e < NE) {
        int d = dst[e];
        int pos = atomicAdd(&g_woff[d], 1);
        g_srcs[pos] = src[e];
    }
}

// ==================== mma helpers ====================
__device__ __forceinline__ void mma16816(float* d, uint32_t a0, uint32_t a1, uint32_t a2,
                                         uint32_t a3, uint32_t b0, uint32_t b1) {
    asm("mma.sync.aligned.m16n8k16.row.col.f32.bf16.bf16.f32 "
        "{%0,%1,%2,%3}, {%4,%5,%6,%7}, {%8,%9}, {%0,%1,%2,%3};"
        : "+f"(d[0]), "+f"(d[1]), "+f"(d[2]), "+f"(d[3])
        : "r"(a0), "r"(a1), "r"(a2), "r"(a3), "r"(b0), "r"(b1));
}
__device__ __forceinline__ void ldsm4(uint32_t& r0, uint32_t& r1, uint32_t& r2, uint32_t& r3,
                                      uint32_t saddr) {
    asm volatile("ldmatrix.sync.aligned.m8n8.x4.shared.b16 {%0,%1,%2,%3}, [%4];"
                 : "=r"(r0), "=r"(r1), "=r"(r2), "=r"(r3) : "r"(saddr));
}

// ==================== pre-GEMM via mma.sync (proven LDS path) ====================
#define PRE_SMEM_B (2304 * 6 * 4)
__global__ void __launch_bounds__(256)
pre_mma_kernel(int layer, const float* __restrict__ pb) {
    extern __shared__ uint32_t smw[];
    uint32_t* Ah = smw;
    uint32_t* Alo = smw + 2304;
    int t = threadIdx.x, lane = t & 31, w = t >> 5;
    int ws = w >> 1, wc = w & 1;
    int node0 = blockIdx.x * 64;
    const uint4* GA4 = (const uint4*)g_A;
    const uint4* GAl4 = (const uint4*)g_Al;
    const uint4* GBp4 = (const uint4*)g_Bp;

    for (int i = t; i < 512; i += 256) {
        int row = i >> 3, seg = i & 7;
        int n = node0 + row;
        if (n > NN - 1) n = NN - 1;
        uint4 va = GA4[(size_t)n * 40 + seg];
        uint4 vl = GAl4[(size_t)n * 40 + seg];
        *(uint4*)(Ah + row * 36 + seg * 4) = va;
        *(uint4*)(Alo + row * 36 + seg * 4) = vl;
    }
    for (int i = t; i < 2048; i += 256) {
        int tidx = i >> 9, r = i & 511;
        int row = r >> 3, seg = r & 7;
        uint4 v = GBp4[((size_t)(layer * 2 + (tidx >> 1)) * 2 + (tidx & 1)) * 512 + r];
        *(uint4*)(smw + 4608 + tidx * 2304 + row * 36 + seg * 4) = v;
    }
    __syncthreads();

    float d[2][4][4];
#pragma unroll
    for (int s = 0; s < 2; s++)
#pragma unroll
        for (int nt = 0; nt < 4; nt++)
#pragma unroll
            for (int q = 0; q < 4; q++) d[s][nt][q] = 0.f;

    int ra = ws * 16 + (lane >> 2);
#pragma unroll 1
    for (int ks = 0; ks < 4; ks++) {
        int kw = ks * 8 + (lane & 3);
        uint32_t ah0 = Ah[ra * 36 + kw],      ah1 = Ah[(ra + 8) * 36 + kw];
        uint32_t ah2 = Ah[ra * 36 + kw + 4],  ah3 = Ah[(ra + 8) * 36 + kw + 4];
        uint32_t al0 = Alo[ra * 36 + kw],     al1 = Alo[(ra + 8) * 36 + kw];
        uint32_t al2 = Alo[ra * 36 + kw + 4], al3 = Alo[(ra + 8) * 36 + kw + 4];
#pragma unroll
        for (int s = 0; s < 2; s++) {
            const uint32_t* Bh = smw + 4608 + s * 2304;
            const uint32_t* Bl = smw + 4608 + (2 + s) * 2304;
#pragma unroll
            for (int nt = 0; nt < 4; nt++) {
                int bi = (wc * 32 + nt * 8 + (lane >> 2)) * 36 + kw;
                uint32_t bh0 = Bh[bi], bh1 = Bh[bi + 4];
                uint32_t bl0 = Bl[bi], bl1 = Bl[bi + 4];
                mma16816(d[s][nt], ah0, ah1, ah2, ah3, bh0, bh1);
                mma16816(d[s][nt], al0, al1, al2, al3, bh0, bh1);
                mma16816(d[s][nt], ah0, ah1, ah2, ah3, bl0, bl1);
            }
        }
    }
#pragma unroll
    for (int half = 0; half < 2; half++) {
        int node = node0 + ra + half * 8;
        if (node >= NN) continue;
#pragma unroll
        for (int s = 0; s < 2; s++)
#pragma unroll
            for (int nt = 0; nt < 4; nt++) {
                int col = wc * 32 + nt * 8 + (lane & 3) * 2;
                float y0 = d[s][nt][2 * half], y1 = d[s][nt][2 * half + 1];
                if (s == 0) { y0 += pb[col]; y1 += pb[col + 1]; }
                *(float2*)(g_ab + (size_t)node * 128 + s * 64 + col) = make_float2(y0, y1);
            }
    }
}

// ==================== aggregation: 4 edges/warp-iter (MLP 2 per half) ====================
__global__ void agg_kernel() {
    int n = (blockIdx.x * blockDim.x + threadIdx.x) >> 5;
    if (n >= NN) return;
    int lane = threadIdx.x & 31;
    int half = lane >> 4, hl = lane & 15;
    int s0 = g_rowptr[n], s1 = g_rowptr[n + 1];
    int deg = s1 - s0;
    float S1[4] = {0.f, 0.f, 0.f, 0.f}, S2[4] = {0.f, 0.f, 0.f, 0.f};
    float MX[4] = {-3.4e38f, -3.4e38f, -3.4e38f, -3.4e38f};
    float MN[4] = {3.4e38f, 3.4e38f, 3.4e38f, 3.4e38f};
    int e = s0 + half;
#pragma unroll 1
    for (; e + 2 < s1; e += 4) {
        int src0 = g_srcs[e];
        int src1 = g_srcs[e + 2];
        float4 v0 = *(const float4*)(g_ab + (size_t)src0 * 128 + 64 + hl * 4);
        float4 v1 = *(const float4*)(g_ab + (size_t)src1 * 128 + 64 + hl * 4);
        S1[0] += v0.x; S2[0] = fmaf(v0.x, v0.x, S2[0]); MX[0] = fmaxf(MX[0], v0.x); MN[0] = fminf(MN[0], v0.x);
        S1[1] += v0.y; S2[1] = fmaf(v0.y, v0.y, S2[1]); MX[1] = fmaxf(MX[1], v0.y); MN[1] = fminf(MN[1], v0.y);
        S1[2] += v0.z; S2[2] = fmaf(v0.z, v0.z, S2[2]); MX[2] = fmaxf(MX[2], v0.z); MN[2] = fminf(MN[2], v0.z);
        S1[3] += v0.w; S2[3] = fmaf(v0.w, v0.w, S2[3]); MX[3] = fmaxf(MX[3], v0.w); MN[3] = fminf(MN[3], v0.w);
        S1[0] += v1.x; S2[0] = fmaf(v1.x, v1.x, S2[0]); MX[0] = fmaxf(MX[0], v1.x); MN[0] = fminf(MN[0], v1.x);
        S1[1] += v1.y; S2[1] = fmaf(v1.y, v1.y, S2[1]); MX[1] = fmaxf(MX[1], v1.y); MN[1] = fminf(MN[1], v1.y);
        S1[2] += v1.z; S2[2] = fmaf(v1.z, v1.z, S2[2]); MX[2] = fmaxf(MX[2], v1.z); MN[2] = fminf(MN[2], v1.z);
        S1[3] += v1.w; S2[3] = fmaf(v1.w, v1.w, S2[3]); MX[3] = fmaxf(MX[3], v1.w); MN[3] = fminf(MN[3], v1.w);
    }
    if (e < s1) {
        int src = g_srcs[e];
        float4 v = *(const float4*)(g_ab + (size_t)src * 128 + 64 + hl * 4);
        S1[0] += v.x; S2[0] = fmaf(v.x, v.x, S2[0]); MX[0] = fmaxf(MX[0], v.x); MN[0] = fminf(MN[0], v.x);
        S1[1] += v.y; S2[1] = fmaf(v.y, v.y, S2[1]); MX[1] = fmaxf(MX[1], v.y); MN[1] = fminf(MN[1], v.y);
        S1[2] += v.z; S2[2] = fmaf(v.z, v.z, S2[2]); MX[2] = fmaxf(MX[2], v.z); MN[2] = fminf(MN[2], v.z);
        S1[3] += v.w; S2[3] = fmaf(v.w, v.w, S2[3]); MX[3] = fmaxf(MX[3], v.w); MN[3] = fminf(MN[3], v.w);
    }
#pragma unroll
    for (int q = 0; q < 4; q++) {
        S1[q] += __shfl_xor_sync(0xffffffffu, S1[q], 16);
        S2[q] += __shfl_xor_sync(0xffffffffu, S2[q], 16);
        MX[q] = fmaxf(MX[q], __shfl_xor_sync(0xffffffffu, MX[q], 16));
        MN[q] = fminf(MN[q], __shfl_xor_sync(0xffffffffu, MN[q], 16));
    }
    float4 av = *(const float4*)(g_ab + (size_t)n * 128 + hl * 4);
    float a[4] = {av.x, av.y, av.z, av.w};
    float degf = (float)deg, degc = fmaxf(degf, 1.f), rdeg = 1.f / degc;
    size_t base = (size_t)n * 320;
#pragma unroll
    for (int which = 0; which < 2; which++) {
        float v[4];
        int s;
        if (half == 0) {
            if (which == 0) {
                s = 0;
#pragma unroll
                for (int q = 0; q < 4; q++) v[q] = (degf * a[q] + S1[q]) * rdeg;
            } else {
                s = 1;
#pragma unroll
                for (int q = 0; q < 4; q++) v[q] = (deg > 0) ? a[q] + MX[q] : 0.f;
            }
        } else {
            if (which == 0) {
                s = 2;
#pragma unroll
                for (int q = 0; q < 4; q++) v[q] = (deg > 0) ? a[q] + MN[q] : 0.f;
            } else {
                s = 3;
#pragma unroll
                for (int q = 0; q < 4; q++) {
                    float mean = (degf * a[q] + S1[q]) * rdeg;
                    float msq = (degf * a[q] * a[q] + 2.f * a[q] * S1[q] + S2[q]) * rdeg;
                    v[q] = sqrtf(fmaxf(msq - mean * mean, 0.f) + 1e-5f);
                }
            }
        }
        uint32_t hu0, hu1, lu0, lu1;
        __nv_bfloat16 hh, ll;
        bsplit(v[0], hh, ll); hu0 = bbits(hh); lu0 = bbits(ll);
        bsplit(v[1], hh, ll); hu0 |= (uint32_t)bbits(hh) << 16; lu0 |= (uint32_t)bbits(ll) << 16;
        bsplit(v[2], hh, ll); hu1 = bbits(hh); lu1 = bbits(ll);
        bsplit(v[3], hh, ll); hu1 |= (uint32_t)bbits(hh) << 16; lu1 |= (uint32_t)bbits(ll) << 16;
        size_t o = base + (size_t)(1 + s) * 64 + hl * 4;
        *(uint2*)(g_A + o) = make_uint2(hu0, hu1);
        *(uint2*)(g_Al + o) = make_uint2(lu0, lu1);
    }
}

// ==================== node GEMM (ldmatrix, M=64) + fused LN / pool epilogue ====
#define NODE_SMEM_W 18432
#define NODE_SMEM_B (NODE_SMEM_W * 4)

__global__ void __launch_bounds__(256)
node_mma_kernel(int layer, int do_ln, const float* __restrict__ lnw,
                const float* __restrict__ lnb, const int* __restrict__ batch) {
    extern __shared__ uint32_t smw[];
    uint32_t* Ah = smw;
    uint32_t* Alo = smw + 2304;
    int t = threadIdx.x, lane = t & 31, w = t >> 5;
    int ws = w >> 1, wc = w & 1;
    int node0 = blockIdx.x * 64;

    float d[3][4][4];
#pragma unroll
    for (int s = 0; s < 3; s++)
#pragma unroll
        for (int nt = 0; nt < 4; nt++)
#pragma unroll
            for (int q = 0; q < 4; q++) d[s][nt][q] = 0.f;

    const uint4* GA4 = (const uint4*)g_A;
    const uint4* GAl4 = (const uint4*)g_Al;
    const uint4* GB4 = (const uint4*)g_B;

    uint32_t sAh = (uint32_t)__cvta_generic_to_shared(Ah);
    uint32_t sAl = (uint32_t)__cvta_generic_to_shared(Alo);
    uint32_t sB0 = (uint32_t)__cvta_generic_to_shared(smw + 4608);

    int m = lane >> 3, rr = lane & 7;
    int ra = ws * 16 + (lane >> 2);

    for (int c = 0; c < 5; c++) {
        __syncthreads();
        for (int i = t; i < 512; i += 256) {
            int row = i >> 3, seg = i & 7;
            int n = node0 + row;
            if (n > NN - 1) n = NN - 1;
            uint4 va = GA4[(size_t)n * 40 + c * 8 + seg];
            uint4 vl = GAl4[(size_t)n * 40 + c * 8 + seg];
            *(uint4*)(Ah + row * 36 + seg * 4) = va;
            *(uint4*)(Alo + row * 36 + seg * 4) = vl;
        }
        int nsets = (c == 0) ? 1 : 3;
        for (int s = 0; s < nsets; s++) {
            int tile = (s == 0) ? c : (s == 1) ? (4 + c) : (8 + c);
            uint32_t* Bh = smw + 4608 + (s * 2 + 0) * 2304;
            uint32_t* Bl = smw + 4608 + (s * 2 + 1) * 2304;
            for (int i = t; i < 512; i += 256) {
                int row = i >> 3, seg = i & 7;
                uint4 vh = GB4[((size_t)(2 * layer + 0) * 13 + tile) * 512 + i];
                uint4 vb = GB4[((size_t)(2 * layer + 1) * 13 + tile) * 512 + i];
                *(uint4*)(Bh + row * 36 + seg * 4) = vh;
                *(uint4*)(Bl + row * 36 + seg * 4) = vb;
            }
        }
        __syncthreads();

#pragma unroll 1
        for (int ks = 0; ks < 4; ks++) {
            uint32_t arow = (uint32_t)((ws * 16 + ((m & 1) << 3) + rr) * 36 + ks * 8 + ((m >> 1) << 2)) << 2;
            uint32_t ah0, ah1, ah2, ah3, al0, al1, al2, al3;
            ldsm4(ah0, ah1, ah2, ah3, sAh + arow);
            ldsm4(al0, al1, al2, al3, sAl + arow);
            uint32_t brow = (uint32_t)((wc * 32 + ((m >> 1) << 3) + rr) * 36 + ks * 8 + ((m & 1) << 2)) << 2;
            uint32_t brow2 = brow + (uint32_t)(16 * 36 * 4);
#pragma unroll
            for (int s = 0; s < 3; s++) {
                if (s > 0 && c == 0) continue;
                uint32_t bhb = sB0 + (uint32_t)((s * 2 + 0) * 2304 * 4);
                uint32_t blb = sB0 + (uint32_t)((s * 2 + 1) * 2304 * 4);
                uint32_t b0, b1, b2, b3, c0, c1, c2, c3;
                ldsm4(b0, b1, b2, b3, bhb + brow);
                ldsm4(c0, c1, c2, c3, blb + brow);
                mma16816(d[s][0], ah0, ah1, ah2, ah3, b0, b1);
                mma16816(d[s][0], al0, al1, al2, al3, b0, b1);
                mma16816(d[s][0], ah0, ah1, ah2, ah3, c0, c1);
                mma16816(d[s][1], ah0, ah1, ah2, ah3, b2, b3);
                mma16816(d[s][1], al0, al1, al2, al3, b2, b3);
                mma16816(d[s][1], ah0, ah1, ah2, ah3, c2, c3);
                ldsm4(b0, b1, b2, b3, bhb + brow2);
                ldsm4(c0, c1, c2, c3, blb + brow2);
                mma16816(d[s][2], ah0, ah1, ah2, ah3, b0, b1);
                mma16816(d[s][2], al0, al1, al2, al3, b0, b1);
                mma16816(d[s][2], ah0, ah1, ah2, ah3, c0, c1);
                mma16816(d[s][3], ah0, ah1, ah2, ah3, b2, b3);
                mma16816(d[s][3], al0, al1, al2, al3, b2, b3);
                mma16816(d[s][3], ah0, ah1, ah2, ah3, c2, c3);
            }
        }
    }

    // ---- epilogue: combine -> smem tile F[64][68] ----
    __syncthreads();
    float* F = (float*)smw;
    const float* b13 = g_W13 + layer * 833 * 64 + 832 * 64;
#pragma unroll
    for (int half = 0; half < 2; half++) {
        int node_local = ra + half * 8;
        int node = node0 + node_local;
        float amp = (node < NN) ? g_amp[node] : 1.f;
        float ramp = 1.f / amp;
#pragma unroll
        for (int nt = 0; nt < 4; nt++) {
            int col = wc * 32 + nt * 8 + (lane & 3) * 2;
            float y0 = d[0][nt][2 * half] + amp * d[1][nt][2 * half]
                     + ramp * d[2][nt][2 * half] + b13[col];
            float y1 = d[0][nt][2 * half + 1] + amp * d[1][nt][2 * half + 1]
                     + ramp * d[2][nt][2 * half + 1] + b13[col + 1];
            F[node_local * 68 + col] = fmaxf(y0, 0.f);
            F[node_local * 68 + col + 1] = fmaxf(y1, 0.f);
        }
    }
    __syncthreads();

    // ---- per-node LN (layers 0,1) or pool (layer 2); warp w owns nodes w*8..w*8+7 ----
    for (int k2 = 0; k2 < 8; k2++) {
        int nl = w * 8 + k2;
        int node = node0 + nl;
        if (node >= NN) continue;
        float v0 = F[nl * 68 + lane], v1 = F[nl * 68 + 32 + lane];
        if (do_ln) {
            float s = v0 + v1;
            for (int o = 16; o > 0; o >>= 1) s += __shfl_xor_sync(0xffffffffu, s, o);
            float mu = s * (1.f / 64.f);
            float d0 = v0 - mu, d1 = v1 - mu;
            float q = d0 * d0 + d1 * d1;
            for (int o = 16; o > 0; o >>= 1) q += __shfl_xor_sync(0xffffffffu, q, o);
            float rstd = rsqrtf(q * (1.f / 64.f) + 1e-5f);
            float o0 = d0 * rstd * lnw[lane] + lnb[lane];
            float o1 = d1 * rstd * lnw[32 + lane] + lnb[32 + lane];
            __nv_bfloat16 h, l;
            bsplit(o0, h, l);
            g_A[(size_t)node * 320 + lane] = h; g_Al[(size_t)node * 320 + lane] = l;
            bsplit(o1, h, l);
            g_A[(size_t)node * 320 + 32 + lane] = h; g_Al[(size_t)node * 320 + 32 + lane] = l;
        } else {
            int g = batch[node];
            atomicAdd(&g_pool[g * 64 + lane], v0);
            atomicAdd(&g_pool[g * 64 + 32 + lane], v1);
            if (lane == 0) atomicAdd(&g_gcnt[g], 1.f);
        }
    }
}

// ==================== final MLP ====================
__global__ void mlp_kernel(const float* __restrict__ w1, const float* __restrict__ b1,
                           const float* __restrict__ w2, const float* __restrict__ b2,
                           float* __restrict__ out) {
    int g = blockIdx.x, t = threadIdx.x;
    float inv = 1.f / fmaxf(g_gcnt[g], 1.f);
    float acc = b1[t];
    for (int k = 0; k < 64; k++) acc = fmaf(g_pool[g * 64 + k] * inv, w1[k * 32 + t], acc);
    acc = fmaxf(acc, 0.f);
    float p = acc * w2[t];
    for (int o = 16; o > 0; o >>= 1) p += __shfl_xor_sync(0xffffffffu, p, o);
    if (t == 0) out[g] = p + b2[0];
}

// ==================== host ====================
extern "C" void kernel_launch(void* const* d_in, const int* in_sizes, int n_in,
                              void* d_out, int out_size) {
    const float* x      = (const float*)d_in[0];
    const int*   esrc   = (const int*)d_in[1];
    const int*   edst   = (const int*)d_in[2];
    const int*   batch  = (const int*)d_in[3];
    const float* pre_w  = (const float*)d_in[4];
    const float* pre_b  = (const float*)d_in[5];
    const float* post_w = (const float*)d_in[6];
    const float* post_b = (const float*)d_in[7];
    const float* lin_w  = (const float*)d_in[8];
    const float* lin_b  = (const float*)d_in[9];
    const float* ln_w   = (const float*)d_in[10];
    const float* ln_b   = (const float*)d_in[11];
    const float* m1w    = (const float*)d_in[12];
    const float* m1b    = (const float*)d_in[13];
    const float* m2w    = (const float*)d_in[14];
    const float* m2b    = (const float*)d_in[15];
    float* out = (float*)d_out;

    cudaFuncSetAttribute(pre_mma_kernel, cudaFuncAttributeMaxDynamicSharedMemorySize, PRE_SMEM_B);
    cudaFuncSetAttribute(node_mma_kernel, cudaFuncAttributeMaxDynamicSharedMemorySize, NODE_SMEM_B);

    zero_front_kernel<<<(NN + 255) / 256, 256>>>();
    split_x_kernel<<<(NN * 64 + 255) / 256, 256>>>(x);
    fold_all_kernel<<<(3 * 833 * 64 + 255) / 256, 256>>>(post_w, post_b, lin_w, lin_b);
    pack_all_kernel<<<(3 * 13 * 4096 + 3 * 2 * 4096 + 255) / 256, 256>>>(pre_w);
    hist_kernel<<<(NE + 255) / 256, 256>>>(edst);
    scan1_kernel<<<NBLK_SCAN, 256>>>();
    scan2_kernel<<<1, 256>>>();
    scan3_kernel<<<NBLK_SCAN, 256>>>();
    scatter_kernel<<<(NE + 255) / 256, 256>>>(edst, esrc);

    const int NB = (NN + 63) / 64;         // 782
    const int WB = (NN * 32 + 255) / 256;  // 6250

    for (int i = 0; i < 3; i++) {
        pre_mma_kernel<<<NB, 256, PRE_SMEM_B>>>(i, pre_b + i * 64);
        agg_kernel<<<WB, 256>>>();
        node_mma_kernel<<<NB, 256, NODE_SMEM_B>>>(i, i < 2, ln_w + i * 64, ln_b + i * 64, batch);
    }
    mlp_kernel<<<NG, 32>>>(m1w, m1b, m2w, m2b, out);
}